// round 14
// baseline (speedup 1.0000x reference)
#include <cuda_runtime.h>
#include <cuda_fp16.h>
#include <cstdint>
#include <math.h>

// Problem constants
#define BB 4
#define SS 2048
#define DD 1024
#define HH 8
#define EE 128
#define HE (HH * EE)   // 1024

// ---------------- scratch (device globals, sized in 32-bit WORDS) ----------------
__device__ unsigned g_qh[(size_t)BB * HH * SS * EE / 2];   // A-pack fp16, Ktot=128
__device__ unsigned g_kh[(size_t)BB * HH * SS * EE / 2];   // B-pack kg-paired (N=key, K=e)
__device__ unsigned g_vh[(size_t)BB * HH * SS * EE / 2];   // V-pack kg-paired (64-key tiles)
__device__ unsigned g_z [(size_t)BB * SS * HE / 2];        // A-pack fp16, Ktot=1024
__device__ unsigned g_qr[(size_t)BB * SS * DD / 2];        // A-pack fp16, Ktot=1024
__device__ unsigned g_kr[(size_t)BB * SS * DD / 2];
__device__ unsigned g_vr[(size_t)BB * SS * DD / 2];
__device__ unsigned g_wq[(size_t)HH * EE * DD / 2];        // B-pack kg-paired per head
__device__ unsigned g_wk[(size_t)HH * EE * DD / 2];
__device__ unsigned g_wv[(size_t)HH * EE * DD / 2];
__device__ unsigned g_wo[(size_t)DD * HE / 2];             // B-pack kg-paired (N=d, K=he)

// ---------------- helpers ----------------
__device__ __forceinline__ unsigned h2(float lo, float hi) {
    __half2 h = __floats2half2_rn(lo, hi);
    return *(unsigned*)&h;
}

__device__ __forceinline__ void mma_f16(float& d0, float& d1, float& d2, float& d3,
                                        unsigned a0, unsigned a1, unsigned a2, unsigned a3,
                                        unsigned b0, unsigned b1)
{
    asm volatile(
        "mma.sync.aligned.m16n8k16.row.col.f32.f16.f16.f32 "
        "{%0,%1,%2,%3}, {%4,%5,%6,%7}, {%8,%9}, {%0,%1,%2,%3};\n"
        : "+f"(d0), "+f"(d1), "+f"(d2), "+f"(d3)
        : "r"(a0), "r"(a1), "r"(a2), "r"(a3), "r"(b0), "r"(b1));
}

__device__ __forceinline__ void cp16(void* smem_dst, const void* gmem_src) {
    unsigned s = (unsigned)__cvta_generic_to_shared(smem_dst);
    asm volatile("cp.async.cg.shared.global [%0], [%1], 16;\n" :: "r"(s), "l"(gmem_src));
}
#define CP_COMMIT() asm volatile("cp.async.commit_group;\n" ::: "memory")
#define CP_WAIT1()  asm volatile("cp.async.wait_group 1;\n" ::: "memory")
#define CP_WAIT0()  asm volatile("cp.async.wait_group 0;\n" ::: "memory")

// =====================================================================
// Pack kernels
// A-pack (unchanged): block 16r x 16k = 128 words, lane holds uint4.
// B-pack kg-paired: block 8n x 32k = 128 words; lane(g=n&7, cc) holds uint4
//   {k=32kb+2cc(+1), k+8, k+16, k+24} all at column n.
// =====================================================================
__global__ __launch_bounds__(256) void packA3(
    const float* __restrict__ a, const float* __restrict__ b, const float* __restrict__ c,
    uint4* __restrict__ A, uint4* __restrict__ B, uint4* __restrict__ C)
{
    const float* src = (blockIdx.y == 0) ? a : (blockIdx.y == 1) ? b : c;
    uint4* dst       = (blockIdx.y == 0) ? A : (blockIdx.y == 1) ? B : C;
    size_t j = (size_t)blockIdx.x * 256 + threadIdx.x;
    int lane = (int)(j & 31);
    size_t blk = j >> 5;
    int g = lane >> 2, cc = lane & 3;
    int R = (int)((blk >> 6) << 4) + g;
    int C0 = (int)((blk & 63) << 4) + 2 * cc;
    uint4 o;
    o.x = h2(src[(size_t)(R    ) * DD + C0    ], src[(size_t)(R    ) * DD + C0 + 1]);
    o.y = h2(src[(size_t)(R + 8) * DD + C0    ], src[(size_t)(R + 8) * DD + C0 + 1]);
    o.z = h2(src[(size_t)(R    ) * DD + C0 + 8], src[(size_t)(R    ) * DD + C0 + 9]);
    o.w = h2(src[(size_t)(R + 8) * DD + C0 + 8], src[(size_t)(R + 8) * DD + C0 + 9]);
    dst[j] = o;
}

// Wq/Wk/Wv [H][D][E] -> kg-paired B-pack per head (N=e: 16 nb, K=d: 32 kb32)
__global__ __launch_bounds__(256) void packB3(
    const float* __restrict__ a, const float* __restrict__ b, const float* __restrict__ c,
    uint4* __restrict__ A, uint4* __restrict__ B, uint4* __restrict__ C)
{
    const float* src = (blockIdx.y == 0) ? a : (blockIdx.y == 1) ? b : c;
    uint4* dst       = (blockIdx.y == 0) ? A : (blockIdx.y == 1) ? B : C;
    size_t j = (size_t)blockIdx.x * 256 + threadIdx.x;   // one uint4
    int h = (int)(j >> 14);                               // 16384 uint4 per head
    size_t jl = j & 16383;
    int lane = (int)(jl & 31);
    int blk = (int)(jl >> 5);                             // nb*32 + kb32
    int g = lane >> 2, cc = lane & 3;
    int N  = ((blk >> 5) << 3) + g;
    int K0 = ((blk & 31) << 5) + 2 * cc;
    const float* sh = src + (size_t)h * DD * EE;
    uint4 o;
    o.x = h2(sh[(size_t)(K0     ) * EE + N], sh[(size_t)(K0 +  1) * EE + N]);
    o.y = h2(sh[(size_t)(K0 +  8) * EE + N], sh[(size_t)(K0 +  9) * EE + N]);
    o.z = h2(sh[(size_t)(K0 + 16) * EE + N], sh[(size_t)(K0 + 17) * EE + N]);
    o.w = h2(sh[(size_t)(K0 + 24) * EE + N], sh[(size_t)(K0 + 25) * EE + N]);
    dst[j] = o;
}

// Wo [HE x DD] -> kg-paired B-pack (N=d: 128 nb, K=he: 32 kb32)
__global__ __launch_bounds__(256) void packBo(
    const float* __restrict__ wo, uint4* __restrict__ dst)
{
    size_t j = (size_t)blockIdx.x * 256 + threadIdx.x;
    int lane = (int)(j & 31);
    int blk = (int)(j >> 5);                              // nb*32 + kb32
    int g = lane >> 2, cc = lane & 3;
    int N  = ((blk >> 5) << 3) + g;
    int K0 = ((blk & 31) << 5) + 2 * cc;
    uint4 o;
    o.x = h2(wo[(size_t)(K0     ) * DD + N], wo[(size_t)(K0 +  1) * DD + N]);
    o.y = h2(wo[(size_t)(K0 +  8) * DD + N], wo[(size_t)(K0 +  9) * DD + N]);
    o.z = h2(wo[(size_t)(K0 + 16) * DD + N], wo[(size_t)(K0 + 17) * DD + N]);
    o.w = h2(wo[(size_t)(K0 + 24) * DD + N], wo[(size_t)(K0 + 25) * DD + N]);
    dst[j] = o;
}

// =====================================================================
// fp16 GEMM core: 256 thr, 8 warps (4x2), warp tile 32x64. 3-stage ring,
// stage = A(4096w) + B(4096w), KC=64 -> 16 iters, 1 sync/iter.
// B fragment loads are LDS.128 covering TWO k16 steps.
// =====================================================================
__device__ __forceinline__ void fill_stage16(
    unsigned* stg, const unsigned* Ap, size_t abase, const unsigned* Bp, size_t bbase,
    int j, int tid)
{
#pragma unroll
    for (int i = 0; i < 4; i++) {
        int flat = tid + i * 256;
        int ablk = flat >> 5, aoff = (flat & 31) * 4;
        int rg = ablk >> 2, kgl = ablk & 3;
        cp16(&stg[ablk * 128 + aoff],
             Ap + abase + (size_t)rg * 8192 + (size_t)(j * 4 + kgl) * 128 + aoff);
    }
#pragma unroll
    for (int i = 0; i < 4; i++) {
        int flat = tid + i * 256;
        int blkI = flat >> 5, boff = (flat & 31) * 4;   // 32 blocks of 128 words
        int nb = blkI >> 1, kp = blkI & 1;
        cp16(&stg[4096 + blkI * 128 + boff],
             Bp + bbase + (size_t)nb * 4096 + (size_t)(j * 2 + kp) * 128 + boff);
    }
}

__device__ __forceinline__ void gemm128h(
    unsigned* S, const unsigned* Ap, size_t abase, const unsigned* Bp, size_t bbase,
    float acc[2][8][4], int tid, int wm, int wn, int lane)
{
    fill_stage16(S,        Ap, abase, Bp, bbase, 0, tid); CP_COMMIT();
    fill_stage16(S + 8192, Ap, abase, Bp, bbase, 1, tid); CP_COMMIT();

    for (int j = 0; j < 16; j++) {
        if (j < 15) { CP_WAIT1(); } else { CP_WAIT0(); }
        __syncthreads();
        if (j + 2 < 16) {
            fill_stage16(S + ((j + 2) % 3) * 8192, Ap, abase, Bp, bbase, j + 2, tid);
            CP_COMMIT();
        }
        const unsigned* As = S + (j % 3) * 8192;
        const unsigned* Bs = As + 4096;
#pragma unroll
        for (int kp = 0; kp < 2; kp++) {
            uint4 a0[2], a1[2];
#pragma unroll
            for (int mi = 0; mi < 2; mi++) {
                a0[mi] = *(const uint4*)(&As[(((wm * 2 + mi) * 4 + kp * 2    ) << 7) + lane * 4]);
                a1[mi] = *(const uint4*)(&As[(((wm * 2 + mi) * 4 + kp * 2 + 1) << 7) + lane * 4]);
            }
#pragma unroll
            for (int jh = 0; jh < 2; jh++) {
                uint4 bq[4];
#pragma unroll
                for (int jj = 0; jj < 4; jj++) {
                    int jt = jh * 4 + jj;
                    bq[jj] = *(const uint4*)(&Bs[(((wn * 8 + jt) * 2 + kp) << 7) + lane * 4]);
                }
#pragma unroll
                for (int mi = 0; mi < 2; mi++)
#pragma unroll
                    for (int jj = 0; jj < 4; jj++) {
                        int jt = jh * 4 + jj;
                        mma_f16(acc[mi][jt][0], acc[mi][jt][1], acc[mi][jt][2], acc[mi][jt][3],
                                a0[mi].x, a0[mi].y, a0[mi].z, a0[mi].w, bq[jj].x, bq[jj].y);
                        mma_f16(acc[mi][jt][0], acc[mi][jt][1], acc[mi][jt][2], acc[mi][jt][3],
                                a1[mi].x, a1[mi].y, a1[mi].z, a1[mi].w, bq[jj].z, bq[jj].w);
                    }
            }
        }
    }
}

#define GEMM_SMEM (3 * 8192 * 4)

// ---- projection GEMM: grid (S/128, 3*B*H) ----
__global__ __launch_bounds__(256, 2) void proj_tc(
    const unsigned* __restrict__ Xq, const unsigned* __restrict__ Xk, const unsigned* __restrict__ Xv,
    const unsigned* __restrict__ Wq, const unsigned* __restrict__ Wk, const unsigned* __restrict__ Wv,
    unsigned* __restrict__ Oq, unsigned* __restrict__ Ok, unsigned* __restrict__ Ov,
    float qscale)
{
    extern __shared__ unsigned smp[];
    int tid = threadIdx.x;
    int warp = tid >> 5, lane = tid & 31;
    int g = lane >> 2, c = lane & 3;
    int wm = warp >> 1, wn = warp & 1;

    int zz = blockIdx.y;
    int which = zz >> 5, bh = zz & 31;
    int b = bh >> 3, h = bh & 7;
    int s0 = blockIdx.x * 128;

    const unsigned* Ap = (which == 0) ? Xq : (which == 1) ? Xk : Xv;
    const unsigned* Bp = (which == 0) ? Wq : (which == 1) ? Wk : Wv;
    unsigned* Out      = (which == 0) ? Oq : (which == 1) ? Ok : Ov;
    float scale        = (which == 0) ? qscale : 1.0f;

    int row0 = b * SS + s0;
    size_t abase = (size_t)(row0 >> 4) * 8192;
    size_t bbase = (size_t)h * 65536;
    unsigned* C = Out + (size_t)bh * 131072;

    float acc[2][8][4];
#pragma unroll
    for (int i = 0; i < 2; i++)
#pragma unroll
        for (int j = 0; j < 8; j++)
#pragma unroll
            for (int t = 0; t < 4; t++) acc[i][j][t] = 0.f;

    gemm128h(smp, Ap, abase, Bp, bbase, acc, tid, wm, wn, lane);

    if (which == 0) {
        // qh A-pack (Ktot=128)
#pragma unroll
        for (int mi = 0; mi < 2; mi++) {
#pragma unroll
            for (int jt = 0; jt < 8; jt++) {
                int R  = s0 + wm * 32 + mi * 16 + g;
                int Cl = wn * 64 + jt * 8 + 2 * c;
                size_t w0 = (size_t)(R >> 4) * 1024 + (size_t)(Cl >> 4) * 128
                          + ((R & 7) * 4 + ((Cl & 7) >> 1)) * 4 + (((Cl >> 3) & 1) << 1);
                uint2 v;
                v.x = h2(acc[mi][jt][0] * scale, acc[mi][jt][1] * scale);
                v.y = h2(acc[mi][jt][2] * scale, acc[mi][jt][3] * scale);
                *(uint2*)(C + w0) = v;
            }
        }
    } else if (which == 1) {
        // kh kg-paired B-pack (N=key, Ktot=128 -> 4 kb32; nb stride 512)
#pragma unroll
        for (int mi = 0; mi < 2; mi++) {
#pragma unroll
            for (int jt = 0; jt < 8; jt++) {
                int R  = s0 + wm * 32 + mi * 16 + g;
                int Cl = wn * 64 + jt * 8 + 2 * c;
                size_t w0 = (size_t)(R >> 3) * 512 + (size_t)(Cl >> 5) * 128
                          + ((R & 7) * 4 + ((Cl & 7) >> 1)) * 4 + ((Cl >> 3) & 3);
                C[w0]       = h2(acc[mi][jt][0], acc[mi][jt][1]);   // key-col R
                C[w0 + 512] = h2(acc[mi][jt][2], acc[mi][jt][3]);   // key-col R+8
            }
        }
    } else {
        // vh kg-paired V-pack: 64-key tiles, nb stride 256, kb32 in {0,1}
#pragma unroll
        for (int mi = 0; mi < 2; mi++) {
#pragma unroll
            for (int jt = 0; jt < 8; jt++) {
                float c0 = acc[mi][jt][0], c1 = acc[mi][jt][1];
                float c2 = acc[mi][jt][2], c3 = acc[mi][jt][3];
                float d0 = __shfl_down_sync(0xffffffffu, c0, 4);
                float d1 = __shfl_down_sync(0xffffffffu, c1, 4);
                float d2 = __shfl_down_sync(0xffffffffu, c2, 4);
                float d3 = __shfl_down_sync(0xffffffffu, c3, 4);
                if ((g & 1) == 0) {
                    int R  = s0 + wm * 32 + mi * 16 + g;
                    int Cl = wn * 64 + jt * 8 + 2 * c;
#pragma unroll
                    for (int rr = 0; rr < 2; rr++) {
                        int Rk = R + rr * 8;
                        float vlo0 = rr ? c2 : c0, vhi0 = rr ? d2 : d0;
                        float vlo1 = rr ? c3 : c1, vhi1 = rr ? d3 : d1;
#pragma unroll
                        for (int nn = 0; nn < 2; nn++) {
                            int n = Cl + nn;
                            size_t w = (size_t)(Rk >> 6) * 4096 + (size_t)(n >> 3) * 256
                                     + (size_t)((Rk & 63) >> 5) * 128
                                     + ((n & 7) * 4 + ((Rk & 7) >> 1)) * 4 + ((Rk >> 3) & 3);
                            C[w] = nn ? h2(vlo1, vhi1) : h2(vlo0, vhi0);
                        }
                    }
                }
            }
        }
    }
}

// ---- output GEMM: Out(fp32) = Z*Wo + bo; grid (D/128, B*S/128) ----
__global__ __launch_bounds__(256, 2) void out_tc(
    const unsigned* __restrict__ Zp, const unsigned* __restrict__ WoP,
    const float* __restrict__ bo, float* __restrict__ Out)
{
    extern __shared__ unsigned smp[];
    int tid = threadIdx.x;
    int warp = tid >> 5, lane = tid & 31;
    int g = lane >> 2, c = lane & 3;
    int wm = warp >> 1, wn = warp & 1;

    int col0 = blockIdx.x * 128;
    int row0 = blockIdx.y * 128;

    size_t abase = (size_t)(row0 >> 4) * 8192;
    size_t bbase = (size_t)(col0 >> 3) * 4096;

    float acc[2][8][4];
#pragma unroll
    for (int i = 0; i < 2; i++)
#pragma unroll
        for (int j = 0; j < 8; j++)
#pragma unroll
            for (int t = 0; t < 4; t++) acc[i][j][t] = 0.f;

    gemm128h(smp, Zp, abase, WoP, bbase, acc, tid, wm, wn, lane);

#pragma unroll
    for (int mi = 0; mi < 2; mi++) {
        int r = row0 + wm * 32 + mi * 16 + g;
#pragma unroll
        for (int jt = 0; jt < 8; jt++) {
            int col = col0 + wn * 64 + jt * 8 + 2 * c;
            float b0 = bo[col], b1 = bo[col + 1];
            *(float2*)(Out + (size_t)r * DD + col) =
                make_float2(acc[mi][jt][0] + b0, acc[mi][jt][1] + b1);
            *(float2*)(Out + (size_t)(r + 8) * DD + col) =
                make_float2(acc[mi][jt][2] + b0, acc[mi][jt][3] + b1);
        }
    }
}

// =====================================================================
// Flash attention v11 (fp16, kg-paired K/V): no max, register l,
// 2 barriers/tile, occupancy 2. All B loads LDS.128.
// =====================================================================
#define FBM 128
#define FBN 64
#define NT (SS / FBN)
#define QW 8192
#define KW 4096
#define VW 4096
#define SPW 4096

extern "C" __global__ __launch_bounds__(256, 2) void flash_tc(
    const unsigned* __restrict__ qh, const unsigned* __restrict__ kh,
    const unsigned* __restrict__ vh, unsigned* __restrict__ z)
{
    extern __shared__ unsigned sm[];
    unsigned* Qs = sm;
    unsigned* Ks = Qs + QW;
    unsigned* Vb = Ks + KW;
    unsigned* SP = Vb + 2 * VW;
    float* ps = (float*)(SP + SPW);

    int bh = blockIdx.y;
    int b = bh >> 3, h = bh & 7;
    int q0 = blockIdx.x * FBM;

    const unsigned* Qg = qh + (size_t)bh * 131072 + (size_t)blockIdx.x * 8192;
    const unsigned* Kg = kh + (size_t)bh * 131072;
    const unsigned* Vg = vh + (size_t)bh * 131072;

    int tid = threadIdx.x;
    int warp = tid >> 5, lane = tid & 31;
    int g = lane >> 2, c = lane & 3;
    int wm = warp >> 1, wn = warp & 1;

    // group 0: Q + K(0); group 1: V(0)
#pragma unroll
    for (int it = 0; it < 8; it++) {
        int w4 = (tid + it * 256) * 4;
        cp16(&Qs[w4], Qg + w4);
    }
#pragma unroll
    for (int it = 0; it < 4; it++) {
        int w4 = (tid + it * 256) * 4;
        cp16(&Ks[w4], Kg + w4);
    }
    CP_COMMIT();
#pragma unroll
    for (int it = 0; it < 4; it++) {
        int w4 = (tid + it * 256) * 4;
        cp16(&Vb[w4], Vg + w4);
    }
    CP_COMMIT();

    float lreg[4];
#pragma unroll
    for (int ri = 0; ri < 4; ri++) lreg[ri] = 0.f;

    float o[2][8][4];
#pragma unroll
    for (int i = 0; i < 2; i++)
#pragma unroll
        for (int j = 0; j < 8; j++)
#pragma unroll
            for (int t = 0; t < 4; t++) o[i][j][t] = 0.f;

    for (int kt = 0; kt < NT; kt++) {
        CP_WAIT1();
        __syncthreads();          // B1: Ks visible; PV(kt-1) done

        // ===== QK^T: S[128x64], warp tile 32x32; K frag = LDS.128 (2 kg) =====
        float sc[2][4][4];
#pragma unroll
        for (int i = 0; i < 2; i++)
#pragma unroll
            for (int j = 0; j < 4; j++)
#pragma unroll
                for (int t = 0; t < 4; t++) sc[i][j][t] = 0.f;

#pragma unroll
        for (int kp = 0; kp < 4; kp++) {
            uint4 bq[4];
#pragma unroll
            for (int jt = 0; jt < 4; jt++)
                bq[jt] = *(const uint4*)(&Ks[(((wn * 4 + jt) * 4 + kp) << 7) + lane * 4]);
#pragma unroll
            for (int mi = 0; mi < 2; mi++) {
                uint4 a0 = *(const uint4*)(&Qs[(((wm * 2 + mi) * 8 + kp * 2    ) << 7) + lane * 4]);
                uint4 a1 = *(const uint4*)(&Qs[(((wm * 2 + mi) * 8 + kp * 2 + 1) << 7) + lane * 4]);
#pragma unroll
                for (int jt = 0; jt < 4; jt++) {
                    mma_f16(sc[mi][jt][0], sc[mi][jt][1], sc[mi][jt][2], sc[mi][jt][3],
                            a0.x, a0.y, a0.z, a0.w, bq[jt].x, bq[jt].y);
                    mma_f16(sc[mi][jt][0], sc[mi][jt][1], sc[mi][jt][2], sc[mi][jt][3],
                            a1.x, a1.y, a1.z, a1.w, bq[jt].z, bq[jt].w);
                }
            }
        }

        // ---- exp (no max), accumulate l, P store (A-pack, unchanged) ----
#pragma unroll
        for (int mi = 0; mi < 2; mi++) {
#pragma unroll
            for (int jt = 0; jt < 4; jt++) {
                float p0 = __expf(sc[mi][jt][0]);
                float p1 = __expf(sc[mi][jt][1]);
                float p2 = __expf(sc[mi][jt][2]);
                float p3 = __expf(sc[mi][jt][3]);
                lreg[mi * 2]     += p0 + p1;
                lreg[mi * 2 + 1] += p2 + p3;
                int base = (((wm * 2 + mi) * 4 + wn * 2 + (jt >> 1)) << 7)
                         + (g * 4 + c) * 4 + ((jt & 1) << 1);
                uint2 v; v.x = h2(p0, p1); v.y = h2(p2, p3);
                *(uint2*)(SP + base) = v;
            }
        }

        CP_WAIT0();               // V(kt) landed
        __syncthreads();          // B2: P + V visible; Ks consumed

        // issue K(kt+1), V(kt+1)
        if (kt + 1 < NT) {
            const unsigned* srck = Kg + (size_t)(kt + 1) * KW;
#pragma unroll
            for (int it = 0; it < 4; it++) {
                int w4 = (tid + it * 256) * 4;
                cp16(&Ks[w4], srck + w4);
            }
            CP_COMMIT();
            const unsigned* srcv = Vg + (size_t)(kt + 1) * VW;
            unsigned* dst = Vb + ((kt + 1) & 1) * VW;
#pragma unroll
            for (int it = 0; it < 4; it++) {
                int w4 = (tid + it * 256) * 4;
                cp16(&dst[w4], srcv + w4);
            }
            CP_COMMIT();
        }

        // ---- PV: O += P*V, warp tile 32x64; V frag = LDS.128 (2 kg) ----
        const unsigned* Vs = Vb + (kt & 1) * VW;
#pragma unroll
        for (int kp = 0; kp < 2; kp++) {
            uint4 a0[2], a1[2];
#pragma unroll
            for (int mi = 0; mi < 2; mi++) {
                a0[mi] = *(const uint4*)(&SP[(((wm * 2 + mi) * 4 + kp * 2    ) << 7) + lane * 4]);
                a1[mi] = *(const uint4*)(&SP[(((wm * 2 + mi) * 4 + kp * 2 + 1) << 7) + lane * 4]);
            }
#pragma unroll
            for (int jh = 0; jh < 2; jh++) {
                uint4 bq[4];
#pragma unroll
                for (int jj = 0; jj < 4; jj++) {
                    int jt = jh * 4 + jj;
                    bq[jj] = *(const uint4*)(&Vs[(((wn * 8 + jt) * 2 + kp) << 7) + lane * 4]);
                }
#pragma unroll
                for (int mi = 0; mi < 2; mi++)
#pragma unroll
                    for (int jj = 0; jj < 4; jj++) {
                        int jt = jh * 4 + jj;
                        mma_f16(o[mi][jt][0], o[mi][jt][1], o[mi][jt][2], o[mi][jt][3],
                                a0[mi].x, a0[mi].y, a0[mi].z, a0[mi].w, bq[jj].x, bq[jj].y);
                        mma_f16(o[mi][jt][0], o[mi][jt][1], o[mi][jt][2], o[mi][jt][3],
                                a1[mi].x, a1[mi].y, a1[mi].z, a1[mi].w, bq[jj].z, bq[jj].w);
                    }
            }
        }
    }

    // ---- final l: reduce over c lanes, combine across wn warps ----
#pragma unroll
    for (int ri = 0; ri < 4; ri++) {
        lreg[ri] += __shfl_xor_sync(0xffffffffu, lreg[ri], 1);
        lreg[ri] += __shfl_xor_sync(0xffffffffu, lreg[ri], 2);
    }
    if (c == 0) {
#pragma unroll
        for (int ri = 0; ri < 4; ri++)
            ps[wn * 128 + wm * 32 + g + ri * 8] = lreg[ri];
    }
    __syncthreads();

    {
        float li[4];
#pragma unroll
        for (int ri = 0; ri < 4; ri++) {
            int row = wm * 32 + g + ri * 8;
            li[ri] = 1.f / (ps[row] + ps[128 + row]);
        }
#pragma unroll
        for (int mi = 0; mi < 2; mi++) {
            float la = li[mi * 2], lb = li[mi * 2 + 1];
#pragma unroll
            for (int jt = 0; jt < 8; jt++) {
                int Rg = b * SS + q0 + wm * 32 + mi * 16 + g;
                int C2 = h * EE + wn * 64 + jt * 8 + 2 * c;
                size_t w0 = (size_t)(Rg >> 4) * 8192 + (size_t)(C2 >> 4) * 128
                          + ((Rg & 7) * 4 + ((C2 & 7) >> 1)) * 4 + (((C2 >> 3) & 1) << 1);
                uint2 v;
                v.x = h2(o[mi][jt][0] * la, o[mi][jt][1] * la);
                v.y = h2(o[mi][jt][2] * lb, o[mi][jt][3] * lb);
                *(uint2*)(z + w0) = v;
            }
        }
    }
}

// =====================================================================
// launch
// =====================================================================
extern "C" void kernel_launch(void* const* d_in, const int* in_sizes, int n_in,
                              void* d_out, int out_size)
{
    const float* q  = (const float*)d_in[0];
    const float* k  = (const float*)d_in[1];
    const float* v  = (const float*)d_in[2];
    const float* Wq = (const float*)d_in[3];
    const float* Wk = (const float*)d_in[4];
    const float* Wv = (const float*)d_in[5];
    const float* Wo = (const float*)d_in[6];
    const float* bo = (const float*)d_in[7];
    float* out = (float*)d_out;

    unsigned *qh, *kh, *vh, *z, *qr, *kr, *vr, *wq, *wk, *wv, *wo;
    cudaGetSymbolAddress((void**)&qh, g_qh);
    cudaGetSymbolAddress((void**)&kh, g_kh);
    cudaGetSymbolAddress((void**)&vh, g_vh);
    cudaGetSymbolAddress((void**)&z,  g_z);
    cudaGetSymbolAddress((void**)&qr, g_qr);
    cudaGetSymbolAddress((void**)&kr, g_kr);
    cudaGetSymbolAddress((void**)&vr, g_vr);
    cudaGetSymbolAddress((void**)&wq, g_wq);
    cudaGetSymbolAddress((void**)&wk, g_wk);
    cudaGetSymbolAddress((void**)&wv, g_wv);
    cudaGetSymbolAddress((void**)&wo, g_wo);

    cudaFuncSetAttribute(proj_tc, cudaFuncAttributeMaxDynamicSharedMemorySize, GEMM_SMEM);
    cudaFuncSetAttribute(out_tc,  cudaFuncAttributeMaxDynamicSharedMemorySize, GEMM_SMEM);
    const int flash_smem = (QW + KW + 2 * VW + SPW + 256) * (int)sizeof(unsigned);
    cudaFuncSetAttribute(flash_tc, cudaFuncAttributeMaxDynamicSharedMemorySize, flash_smem);

    float qscale = 1.0f / sqrtf((float)EE);

    {
        dim3 ga((BB * SS * DD / 8) / 256, 3);
        packA3<<<ga, 256>>>(q, k, v, (uint4*)qr, (uint4*)kr, (uint4*)vr);
        dim3 gb((HH * DD * EE / 8) / 256, 3);
        packB3<<<gb, 256>>>(Wq, Wk, Wv, (uint4*)wq, (uint4*)wk, (uint4*)wv);
        packBo<<<(HE * DD / 8) / 256, 256>>>(Wo, (uint4*)wo);
    }

    dim3 pgrid(SS / 128, 3 * BB * HH);
    proj_tc<<<pgrid, 256, GEMM_SMEM>>>(qr, kr, vr, wq, wk, wv, qh, kh, vh, qscale);

    dim3 fgrid(SS / FBM, BB * HH);
    flash_tc<<<fgrid, 256, flash_smem>>>(qh, kh, vh, z);

    dim3 ogrid(DD / 128, (BB * SS) / 128);
    out_tc<<<ogrid, 256, GEMM_SMEM>>>(z, wo, bo, out);
}

// round 15
// speedup vs baseline: 1.0752x; 1.0752x over previous
#include <cuda_runtime.h>
#include <cuda_fp16.h>
#include <cstdint>
#include <math.h>

// Problem constants
#define BB 4
#define SS 2048
#define DD 1024
#define HH 8
#define EE 128
#define HE (HH * EE)   // 1024

// ---------------- scratch (device globals, sized in 32-bit WORDS) ----------------
__device__ unsigned g_qh[(size_t)BB * HH * SS * EE / 2];   // A-pack fp16, Ktot=128
__device__ unsigned g_kh[(size_t)BB * HH * SS * EE / 2];   // B-pack fp16 (N=key, K=e)
__device__ unsigned g_vh[(size_t)BB * HH * SS * EE / 2];   // V-pack fp16 (64-key tiles)
__device__ unsigned g_z [(size_t)BB * SS * HE / 2];        // A-pack fp16, Ktot=1024
__device__ unsigned g_qr[(size_t)BB * SS * DD / 2];        // A-pack fp16, Ktot=1024
__device__ unsigned g_kr[(size_t)BB * SS * DD / 2];
__device__ unsigned g_vr[(size_t)BB * SS * DD / 2];
__device__ unsigned g_wq[(size_t)HH * EE * DD / 2];        // B-pack fp16 per head
__device__ unsigned g_wk[(size_t)HH * EE * DD / 2];
__device__ unsigned g_wv[(size_t)HH * EE * DD / 2];
__device__ unsigned g_wo[(size_t)DD * HE / 2];             // B-pack fp16 (N=d, K=he)

// ---------------- helpers ----------------
__device__ __forceinline__ unsigned h2(float lo, float hi) {
    __half2 h = __floats2half2_rn(lo, hi);
    return *(unsigned*)&h;
}

__device__ __forceinline__ void mma_f16(float& d0, float& d1, float& d2, float& d3,
                                        unsigned a0, unsigned a1, unsigned a2, unsigned a3,
                                        unsigned b0, unsigned b1)
{
    asm volatile(
        "mma.sync.aligned.m16n8k16.row.col.f32.f16.f16.f32 "
        "{%0,%1,%2,%3}, {%4,%5,%6,%7}, {%8,%9}, {%0,%1,%2,%3};\n"
        : "+f"(d0), "+f"(d1), "+f"(d2), "+f"(d3)
        : "r"(a0), "r"(a1), "r"(a2), "r"(a3), "r"(b0), "r"(b1));
}

__device__ __forceinline__ void cp16(void* smem_dst, const void* gmem_src) {
    unsigned s = (unsigned)__cvta_generic_to_shared(smem_dst);
    asm volatile("cp.async.cg.shared.global [%0], [%1], 16;\n" :: "r"(s), "l"(gmem_src));
}
#define CP_COMMIT() asm volatile("cp.async.commit_group;\n" ::: "memory")
#define CP_WAIT1()  asm volatile("cp.async.wait_group 1;\n" ::: "memory")
#define CP_WAIT0()  asm volatile("cp.async.wait_group 0;\n" ::: "memory")

// =====================================================================
// Pack kernels (identical to round 13)
// =====================================================================
__global__ __launch_bounds__(256) void packA3(
    const float* __restrict__ a, const float* __restrict__ b, const float* __restrict__ c,
    uint4* __restrict__ A, uint4* __restrict__ B, uint4* __restrict__ C)
{
    const float* src = (blockIdx.y == 0) ? a : (blockIdx.y == 1) ? b : c;
    uint4* dst       = (blockIdx.y == 0) ? A : (blockIdx.y == 1) ? B : C;
    size_t j = (size_t)blockIdx.x * 256 + threadIdx.x;
    int lane = (int)(j & 31);
    size_t blk = j >> 5;
    int g = lane >> 2, cc = lane & 3;
    int R = (int)((blk >> 6) << 4) + g;
    int C0 = (int)((blk & 63) << 4) + 2 * cc;
    uint4 o;
    o.x = h2(src[(size_t)(R    ) * DD + C0    ], src[(size_t)(R    ) * DD + C0 + 1]);
    o.y = h2(src[(size_t)(R + 8) * DD + C0    ], src[(size_t)(R + 8) * DD + C0 + 1]);
    o.z = h2(src[(size_t)(R    ) * DD + C0 + 8], src[(size_t)(R    ) * DD + C0 + 9]);
    o.w = h2(src[(size_t)(R + 8) * DD + C0 + 8], src[(size_t)(R + 8) * DD + C0 + 9]);
    dst[j] = o;
}

__global__ __launch_bounds__(256) void packB3(
    const float* __restrict__ a, const float* __restrict__ b, const float* __restrict__ c,
    uint2* __restrict__ A, uint2* __restrict__ B, uint2* __restrict__ C)
{
    const float* src = (blockIdx.y == 0) ? a : (blockIdx.y == 1) ? b : c;
    uint2* dst       = (blockIdx.y == 0) ? A : (blockIdx.y == 1) ? B : C;
    size_t j = (size_t)blockIdx.x * 256 + threadIdx.x;
    int h = (int)(j >> 15);
    size_t jl = j & 32767;
    int lane = (int)(jl & 31);
    int blk = (int)(jl >> 5);
    int g = lane >> 2, cc = lane & 3;
    int N  = ((blk >> 6) << 3) + g;
    int K2 = ((blk & 63) << 4) + 2 * cc;
    const float* sh = src + (size_t)h * DD * EE;
    uint2 o;
    o.x = h2(sh[(size_t)(K2    ) * EE + N], sh[(size_t)(K2 + 1) * EE + N]);
    o.y = h2(sh[(size_t)(K2 + 8) * EE + N], sh[(size_t)(K2 + 9) * EE + N]);
    dst[j] = o;
}

__global__ __launch_bounds__(256) void packBo(
    const float* __restrict__ wo, uint2* __restrict__ dst)
{
    size_t j = (size_t)blockIdx.x * 256 + threadIdx.x;
    int lane = (int)(j & 31);
    int blk = (int)(j >> 5);
    int g = lane >> 2, cc = lane & 3;
    int N  = ((blk >> 6) << 3) + g;
    int K2 = ((blk & 63) << 4) + 2 * cc;
    uint2 o;
    o.x = h2(wo[(size_t)(K2    ) * DD + N], wo[(size_t)(K2 + 1) * DD + N]);
    o.y = h2(wo[(size_t)(K2 + 8) * DD + N], wo[(size_t)(K2 + 9) * DD + N]);
    dst[j] = o;
}

// =====================================================================
// fp16 GEMM core: 256 thr, 8 warps in 2x4 grid, warp tile 64x32.
// Same smem layout as r13; B-frag LDS count halved vs 32x64.
// =====================================================================
__device__ __forceinline__ void fill_stage16(
    unsigned* stg, const unsigned* Ap, size_t abase, const unsigned* Bp, size_t bbase,
    int j, int tid)
{
#pragma unroll
    for (int i = 0; i < 4; i++) {
        int flat = tid + i * 256;
        int ablk = flat >> 5, aoff = (flat & 31) * 4;
        int rg = ablk >> 2, kgl = ablk & 3;
        cp16(&stg[ablk * 128 + aoff],
             Ap + abase + (size_t)rg * 8192 + (size_t)(j * 4 + kgl) * 128 + aoff);
    }
#pragma unroll
    for (int i = 0; i < 4; i++) {
        int flat = tid + i * 256;
        int bblk = flat >> 4, boff = (flat & 15) * 4;
        int ng = bblk >> 2, kgl = bblk & 3;
        cp16(&stg[4096 + bblk * 64 + boff],
             Bp + bbase + (size_t)ng * 4096 + (size_t)(j * 4 + kgl) * 64 + boff);
    }
}

__device__ __forceinline__ void gemm128h(
    unsigned* S, const unsigned* Ap, size_t abase, const unsigned* Bp, size_t bbase,
    float acc[4][4][4], int tid, int wm, int wn, int lane)
{
    fill_stage16(S,        Ap, abase, Bp, bbase, 0, tid); CP_COMMIT();
    fill_stage16(S + 8192, Ap, abase, Bp, bbase, 1, tid); CP_COMMIT();

    for (int j = 0; j < 16; j++) {
        if (j < 15) { CP_WAIT1(); } else { CP_WAIT0(); }
        __syncthreads();
        if (j + 2 < 16) {
            fill_stage16(S + ((j + 2) % 3) * 8192, Ap, abase, Bp, bbase, j + 2, tid);
            CP_COMMIT();
        }
        const unsigned* As = S + (j % 3) * 8192;
        const unsigned* Bs = As + 4096;
#pragma unroll
        for (int kg = 0; kg < 4; kg++) {
            uint4 a[4];
#pragma unroll
            for (int mi = 0; mi < 4; mi++)
                a[mi] = *(const uint4*)(&As[(((wm * 4 + mi) * 4 + kg) << 7) + lane * 4]);
            uint2 bf[4];
#pragma unroll
            for (int jt = 0; jt < 4; jt++)
                bf[jt] = *(const uint2*)(&Bs[(((wn * 4 + jt) * 4 + kg) << 6) + lane * 2]);
#pragma unroll
            for (int mi = 0; mi < 4; mi++)
#pragma unroll
                for (int jt = 0; jt < 4; jt++)
                    mma_f16(acc[mi][jt][0], acc[mi][jt][1], acc[mi][jt][2], acc[mi][jt][3],
                            a[mi].x, a[mi].y, a[mi].z, a[mi].w,
                            bf[jt].x, bf[jt].y);
        }
    }
}

#define GEMM_SMEM (3 * 8192 * 4)

// ---- projection GEMM: grid (S/128, 3*B*H) ----
__global__ __launch_bounds__(256, 2) void proj_tc(
    const unsigned* __restrict__ Xq, const unsigned* __restrict__ Xk, const unsigned* __restrict__ Xv,
    const unsigned* __restrict__ Wq, const unsigned* __restrict__ Wk, const unsigned* __restrict__ Wv,
    unsigned* __restrict__ Oq, unsigned* __restrict__ Ok, unsigned* __restrict__ Ov,
    float qscale)
{
    extern __shared__ unsigned smp[];
    int tid = threadIdx.x;
    int warp = tid >> 5, lane = tid & 31;
    int g = lane >> 2, c = lane & 3;
    int wm = warp >> 2, wn = warp & 3;   // 2x4 grid, tile 64x32

    int zz = blockIdx.y;
    int which = zz >> 5, bh = zz & 31;
    int b = bh >> 3, h = bh & 7;
    int s0 = blockIdx.x * 128;

    const unsigned* Ap = (which == 0) ? Xq : (which == 1) ? Xk : Xv;
    const unsigned* Bp = (which == 0) ? Wq : (which == 1) ? Wk : Wv;
    unsigned* Out      = (which == 0) ? Oq : (which == 1) ? Ok : Ov;
    float scale        = (which == 0) ? qscale : 1.0f;

    int row0 = b * SS + s0;
    size_t abase = (size_t)(row0 >> 4) * 8192;
    size_t bbase = (size_t)h * 65536;
    unsigned* C = Out + (size_t)bh * 131072;

    float acc[4][4][4];
#pragma unroll
    for (int i = 0; i < 4; i++)
#pragma unroll
        for (int j = 0; j < 4; j++)
#pragma unroll
            for (int t = 0; t < 4; t++) acc[i][j][t] = 0.f;

    gemm128h(smp, Ap, abase, Bp, bbase, acc, tid, wm, wn, lane);

    if (which == 0) {
#pragma unroll
        for (int mi = 0; mi < 4; mi++) {
#pragma unroll
            for (int jt = 0; jt < 4; jt++) {
                int R  = s0 + wm * 64 + mi * 16 + g;
                int Cl = wn * 32 + jt * 8 + 2 * c;
                size_t w0 = (size_t)(R >> 4) * 1024 + (size_t)(Cl >> 4) * 128
                          + ((R & 7) * 4 + ((Cl & 7) >> 1)) * 4 + (((Cl >> 3) & 1) << 1);
                uint2 v;
                v.x = h2(acc[mi][jt][0] * scale, acc[mi][jt][1] * scale);
                v.y = h2(acc[mi][jt][2] * scale, acc[mi][jt][3] * scale);
                *(uint2*)(C + w0) = v;
            }
        }
    } else if (which == 1) {
#pragma unroll
        for (int mi = 0; mi < 4; mi++) {
#pragma unroll
            for (int jt = 0; jt < 4; jt++) {
                int R  = s0 + wm * 64 + mi * 16 + g;
                int Cl = wn * 32 + jt * 8 + 2 * c;
                size_t w0 = (size_t)(R >> 3) * 512 + (size_t)(Cl >> 4) * 64
                          + ((R & 7) * 4 + ((Cl & 7) >> 1)) * 2 + ((Cl >> 3) & 1);
                C[w0]       = h2(acc[mi][jt][0], acc[mi][jt][1]);
                C[w0 + 512] = h2(acc[mi][jt][2], acc[mi][jt][3]);
            }
        }
    } else {
#pragma unroll
        for (int mi = 0; mi < 4; mi++) {
#pragma unroll
            for (int jt = 0; jt < 4; jt++) {
                float c0 = acc[mi][jt][0], c1 = acc[mi][jt][1];
                float c2 = acc[mi][jt][2], c3 = acc[mi][jt][3];
                float d0 = __shfl_down_sync(0xffffffffu, c0, 4);
                float d1 = __shfl_down_sync(0xffffffffu, c1, 4);
                float d2 = __shfl_down_sync(0xffffffffu, c2, 4);
                float d3 = __shfl_down_sync(0xffffffffu, c3, 4);
                if ((g & 1) == 0) {
                    int R  = s0 + wm * 64 + mi * 16 + g;
                    int Cl = wn * 32 + jt * 8 + 2 * c;
#pragma unroll
                    for (int rr = 0; rr < 2; rr++) {
                        int Rk = R + rr * 8;
                        float vlo0 = rr ? c2 : c0, vhi0 = rr ? d2 : d0;
                        float vlo1 = rr ? c3 : c1, vhi1 = rr ? d3 : d1;
#pragma unroll
                        for (int nn = 0; nn < 2; nn++) {
                            int n = Cl + nn;
                            size_t w = (size_t)(Rk >> 6) * 4096 + (size_t)(n >> 3) * 256
                                     + ((Rk >> 4) & 3) * 64
                                     + ((n & 7) * 4 + ((Rk & 7) >> 1)) * 2 + ((Rk >> 3) & 1);
                            C[w] = nn ? h2(vlo1, vhi1) : h2(vlo0, vhi0);
                        }
                    }
                }
            }
        }
    }
}

// ---- output GEMM: Out(fp32) = Z*Wo + bo; grid (D/128, B*S/128) ----
__global__ __launch_bounds__(256, 2) void out_tc(
    const unsigned* __restrict__ Zp, const unsigned* __restrict__ WoP,
    const float* __restrict__ bo, float* __restrict__ Out)
{
    extern __shared__ unsigned smp[];
    int tid = threadIdx.x;
    int warp = tid >> 5, lane = tid & 31;
    int g = lane >> 2, c = lane & 3;
    int wm = warp >> 2, wn = warp & 3;   // 2x4 grid, tile 64x32

    int col0 = blockIdx.x * 128;
    int row0 = blockIdx.y * 128;

    size_t abase = (size_t)(row0 >> 4) * 8192;
    size_t bbase = (size_t)(col0 >> 3) * 4096;

    float acc[4][4][4];
#pragma unroll
    for (int i = 0; i < 4; i++)
#pragma unroll
        for (int j = 0; j < 4; j++)
#pragma unroll
            for (int t = 0; t < 4; t++) acc[i][j][t] = 0.f;

    gemm128h(smp, Zp, abase, WoP, bbase, acc, tid, wm, wn, lane);

#pragma unroll
    for (int mi = 0; mi < 4; mi++) {
        int r = row0 + wm * 64 + mi * 16 + g;
#pragma unroll
        for (int jt = 0; jt < 4; jt++) {
            int col = col0 + wn * 32 + jt * 8 + 2 * c;
            float b0 = bo[col], b1 = bo[col + 1];
            *(float2*)(Out + (size_t)r * DD + col) =
                make_float2(acc[mi][jt][0] + b0, acc[mi][jt][1] + b1);
            *(float2*)(Out + (size_t)(r + 8) * DD + col) =
                make_float2(acc[mi][jt][2] + b0, acc[mi][jt][3] + b1);
        }
    }
}

// =====================================================================
// Flash attention v12 (fp16): QK 32x32 (4x2 grid), PV 64x32 (2x4 grid),
// no max, register l, 2 barriers/tile, occupancy 2. r13 layouts.
// =====================================================================
#define FBM 128
#define FBN 64
#define NT (SS / FBN)
#define QW 8192
#define KW 4096
#define VW 4096
#define SPW 4096

extern "C" __global__ __launch_bounds__(256, 2) void flash_tc(
    const unsigned* __restrict__ qh, const unsigned* __restrict__ kh,
    const unsigned* __restrict__ vh, unsigned* __restrict__ z)
{
    extern __shared__ unsigned sm[];
    unsigned* Qs = sm;
    unsigned* Ks = Qs + QW;
    unsigned* Vb = Ks + KW;
    unsigned* SP = Vb + 2 * VW;
    float* ps = (float*)(SP + SPW);   // 2 x 128 row-sum partials

    int bh = blockIdx.y;
    int b = bh >> 3, h = bh & 7;
    int q0 = blockIdx.x * FBM;

    const unsigned* Qg = qh + (size_t)bh * 131072 + (size_t)blockIdx.x * 8192;
    const unsigned* Kg = kh + (size_t)bh * 131072;
    const unsigned* Vg = vh + (size_t)bh * 131072;

    int tid = threadIdx.x;
    int warp = tid >> 5, lane = tid & 31;
    int g = lane >> 2, c = lane & 3;
    int wm = warp >> 1, wn = warp & 1;   // QK grid 4x2 (32x32 tiles)
    int pm = warp >> 2, pn = warp & 3;   // PV grid 2x4 (64x32 tiles)

    // group 0: Q + K(0); group 1: V(0)
#pragma unroll
    for (int it = 0; it < 8; it++) {
        int w4 = (tid + it * 256) * 4;
        cp16(&Qs[w4], Qg + w4);
    }
#pragma unroll
    for (int it = 0; it < 4; it++) {
        int w4 = (tid + it * 256) * 4;
        cp16(&Ks[w4], Kg + w4);
    }
    CP_COMMIT();
#pragma unroll
    for (int it = 0; it < 4; it++) {
        int w4 = (tid + it * 256) * 4;
        cp16(&Vb[w4], Vg + w4);
    }
    CP_COMMIT();

    float lreg[4];
#pragma unroll
    for (int ri = 0; ri < 4; ri++) lreg[ri] = 0.f;

    float o[4][4][4];   // PV: rows pm*64 + mi*16 + g(+8), cols pn*32 + jt*8
#pragma unroll
    for (int i = 0; i < 4; i++)
#pragma unroll
        for (int j = 0; j < 4; j++)
#pragma unroll
            for (int t = 0; t < 4; t++) o[i][j][t] = 0.f;

    for (int kt = 0; kt < NT; kt++) {
        CP_WAIT1();
        __syncthreads();          // B1: Ks visible; PV(kt-1) done (SP free)

        // ===== QK^T: S[128x64], warp tile 32x32, 8 k16 groups =====
        float sc[2][4][4];
#pragma unroll
        for (int i = 0; i < 2; i++)
#pragma unroll
            for (int j = 0; j < 4; j++)
#pragma unroll
                for (int t = 0; t < 4; t++) sc[i][j][t] = 0.f;

#pragma unroll
        for (int kg = 0; kg < 8; kg++) {
            uint4 a[2];
#pragma unroll
            for (int mi = 0; mi < 2; mi++)
                a[mi] = *(const uint4*)(&Qs[(((wm * 2 + mi) * 8 + kg) << 7) + lane * 4]);
            uint2 bf[4];
#pragma unroll
            for (int jt = 0; jt < 4; jt++)
                bf[jt] = *(const uint2*)(&Ks[(((wn * 4 + jt) * 8 + kg) << 6) + lane * 2]);
#pragma unroll
            for (int mi = 0; mi < 2; mi++)
#pragma unroll
                for (int jt = 0; jt < 4; jt++)
                    mma_f16(sc[mi][jt][0], sc[mi][jt][1], sc[mi][jt][2], sc[mi][jt][3],
                            a[mi].x, a[mi].y, a[mi].z, a[mi].w,
                            bf[jt].x, bf[jt].y);
        }

        // ---- exp (no max), accumulate l, P store (A-pack) ----
#pragma unroll
        for (int mi = 0; mi < 2; mi++) {
#pragma unroll
            for (int jt = 0; jt < 4; jt++) {
                float p0 = __expf(sc[mi][jt][0]);
                float p1 = __expf(sc[mi][jt][1]);
                float p2 = __expf(sc[mi][jt][2]);
                float p3 = __expf(sc[mi][jt][3]);
                lreg[mi * 2]     += p0 + p1;
                lreg[mi * 2 + 1] += p2 + p3;
                int base = (((wm * 2 + mi) * 4 + wn * 2 + (jt >> 1)) << 7)
                         + (g * 4 + c) * 4 + ((jt & 1) << 1);
                uint2 v; v.x = h2(p0, p1); v.y = h2(p2, p3);
                *(uint2*)(SP + base) = v;
            }
        }

        CP_WAIT0();               // V(kt) landed
        __syncthreads();          // B2: P + V visible; Ks consumed

        // issue K(kt+1), V(kt+1)
        if (kt + 1 < NT) {
            const unsigned* srck = Kg + (size_t)(kt + 1) * KW;
#pragma unroll
            for (int it = 0; it < 4; it++) {
                int w4 = (tid + it * 256) * 4;
                cp16(&Ks[w4], srck + w4);
            }
            CP_COMMIT();
            const unsigned* srcv = Vg + (size_t)(kt + 1) * VW;
            unsigned* dst = Vb + ((kt + 1) & 1) * VW;
#pragma unroll
            for (int it = 0; it < 4; it++) {
                int w4 = (tid + it * 256) * 4;
                cp16(&dst[w4], srcv + w4);
            }
            CP_COMMIT();
        }

        // ---- PV: O += P*V, warp tile 64x32 (2x4 grid), 4 k16 groups ----
        const unsigned* Vs = Vb + (kt & 1) * VW;
#pragma unroll
        for (int kq = 0; kq < 4; kq++) {
            uint4 a[4];
#pragma unroll
            for (int mi = 0; mi < 4; mi++)
                a[mi] = *(const uint4*)(&SP[(((pm * 4 + mi) * 4 + kq) << 7) + lane * 4]);
            uint2 bf[4];
#pragma unroll
            for (int jt = 0; jt < 4; jt++)
                bf[jt] = *(const uint2*)(&Vs[(((pn * 4 + jt) * 4 + kq) << 6) + lane * 2]);
#pragma unroll
            for (int mi = 0; mi < 4; mi++)
#pragma unroll
                for (int jt = 0; jt < 4; jt++)
                    mma_f16(o[mi][jt][0], o[mi][jt][1], o[mi][jt][2], o[mi][jt][3],
                            a[mi].x, a[mi].y, a[mi].z, a[mi].w,
                            bf[jt].x, bf[jt].y);
        }
    }

    // ---- final l: reduce over c lanes, publish (QK row ownership) ----
#pragma unroll
    for (int ri = 0; ri < 4; ri++) {
        lreg[ri] += __shfl_xor_sync(0xffffffffu, lreg[ri], 1);
        lreg[ri] += __shfl_xor_sync(0xffffffffu, lreg[ri], 2);
    }
    if (c == 0) {
#pragma unroll
        for (int ri = 0; ri < 4; ri++)
            ps[wn * 128 + wm * 32 + g + ri * 8] = lreg[ri];
    }
    __syncthreads();

    // ---- divide + store z A-packed (PV row ownership) ----
    {
#pragma unroll
        for (int mi = 0; mi < 4; mi++) {
            int rbase = pm * 64 + mi * 16 + g;
            float la = 1.f / (ps[rbase] + ps[128 + rbase]);
            float lb = 1.f / (ps[rbase + 8] + ps[128 + rbase + 8]);
#pragma unroll
            for (int jt = 0; jt < 4; jt++) {
                int Rg = b * SS + q0 + rbase;
                int C2 = h * EE + pn * 32 + jt * 8 + 2 * c;
                size_t w0 = (size_t)(Rg >> 4) * 8192 + (size_t)(C2 >> 4) * 128
                          + ((Rg & 7) * 4 + ((C2 & 7) >> 1)) * 4 + (((C2 >> 3) & 1) << 1);
                uint2 v;
                v.x = h2(o[mi][jt][0] * la, o[mi][jt][1] * la);
                v.y = h2(o[mi][jt][2] * lb, o[mi][jt][3] * lb);
                *(uint2*)(z + w0) = v;
            }
        }
    }
}

// =====================================================================
// launch
// =====================================================================
extern "C" void kernel_launch(void* const* d_in, const int* in_sizes, int n_in,
                              void* d_out, int out_size)
{
    const float* q  = (const float*)d_in[0];
    const float* k  = (const float*)d_in[1];
    const float* v  = (const float*)d_in[2];
    const float* Wq = (const float*)d_in[3];
    const float* Wk = (const float*)d_in[4];
    const float* Wv = (const float*)d_in[5];
    const float* Wo = (const float*)d_in[6];
    const float* bo = (const float*)d_in[7];
    float* out = (float*)d_out;

    unsigned *qh, *kh, *vh, *z, *qr, *kr, *vr, *wq, *wk, *wv, *wo;
    cudaGetSymbolAddress((void**)&qh, g_qh);
    cudaGetSymbolAddress((void**)&kh, g_kh);
    cudaGetSymbolAddress((void**)&vh, g_vh);
    cudaGetSymbolAddress((void**)&z,  g_z);
    cudaGetSymbolAddress((void**)&qr, g_qr);
    cudaGetSymbolAddress((void**)&kr, g_kr);
    cudaGetSymbolAddress((void**)&vr, g_vr);
    cudaGetSymbolAddress((void**)&wq, g_wq);
    cudaGetSymbolAddress((void**)&wk, g_wk);
    cudaGetSymbolAddress((void**)&wv, g_wv);
    cudaGetSymbolAddress((void**)&wo, g_wo);

    cudaFuncSetAttribute(proj_tc, cudaFuncAttributeMaxDynamicSharedMemorySize, GEMM_SMEM);
    cudaFuncSetAttribute(out_tc,  cudaFuncAttributeMaxDynamicSharedMemorySize, GEMM_SMEM);
    const int flash_smem = (QW + KW + 2 * VW + SPW + 256) * (int)sizeof(unsigned);
    cudaFuncSetAttribute(flash_tc, cudaFuncAttributeMaxDynamicSharedMemorySize, flash_smem);

    float qscale = 1.0f / sqrtf((float)EE);

    {
        dim3 ga((BB * SS * DD / 8) / 256, 3);
        packA3<<<ga, 256>>>(q, k, v, (uint4*)qr, (uint4*)kr, (uint4*)vr);
        dim3 gb((HH * DD * EE / 4) / 256, 3);
        packB3<<<gb, 256>>>(Wq, Wk, Wv, (uint2*)wq, (uint2*)wk, (uint2*)wv);
        packBo<<<(HE * DD / 4) / 256, 256>>>(Wo, (uint2*)wo);
    }

    dim3 pgrid(SS / 128, 3 * BB * HH);
    proj_tc<<<pgrid, 256, GEMM_SMEM>>>(qr, kr, vr, wq, wk, wv, qh, kh, vh, qscale);

    dim3 fgrid(SS / FBM, BB * HH);
    flash_tc<<<fgrid, 256, flash_smem>>>(qh, kh, vh, z);

    dim3 ogrid(DD / 128, (BB * SS) / 128);
    out_tc<<<ogrid, 256, GEMM_SMEM>>>(z, wo, bo, out);
}